// round 3
// baseline (speedup 1.0000x reference)
#include <cuda_runtime.h>
#include <stdint.h>

#define NROWS 8192
#define DIM   768
#define EPSN  1e-8f

#define BM 128
#define BN 128
#define BK 8
#define TM 8
#define TN 8

// Scratch (allocation-free per harness rules): normalized copies + max keys.
__device__ float        g_exn[(size_t)NROWS * DIM];
__device__ float        g_eyn[(size_t)NROWS * DIM];
__device__ unsigned int g_keys[NROWS];

// Order-preserving float -> uint key (monotone for all finite floats).
__device__ __forceinline__ unsigned int fkey(float f) {
    unsigned int b = __float_as_uint(f);
    return (b & 0x80000000u) ? ~b : (b | 0x80000000u);
}

__global__ void init_keys_kernel() {
    int i = blockIdx.x * blockDim.x + threadIdx.x;
    if (i < NROWS) g_keys[i] = 0u;   // maps to very negative float; safe lower bound
}

// One block per row (16384 blocks). 192 threads, one float4 each (768 = 192*4).
__global__ __launch_bounds__(192) void normalize_kernel(
    const float* __restrict__ ex, const float* __restrict__ ey)
{
    int row = blockIdx.x;
    const float* src = (row < NROWS) ? (ex + (size_t)row * DIM)
                                     : (ey + (size_t)(row - NROWS) * DIM);
    float* dst       = (row < NROWS) ? (g_exn + (size_t)row * DIM)
                                     : (g_eyn + (size_t)(row - NROWS) * DIM);
    int t = threadIdx.x;
    float4 v = ((const float4*)src)[t];
    float ss = v.x * v.x + v.y * v.y + v.z * v.z + v.w * v.w;
    #pragma unroll
    for (int o = 16; o > 0; o >>= 1) ss += __shfl_xor_sync(0xffffffffu, ss, o);

    __shared__ float wsum[6];
    __shared__ float s_scale;
    int w = t >> 5, l = t & 31;
    if (l == 0) wsum[w] = ss;
    __syncthreads();
    if (t == 0) {
        float tot = wsum[0] + wsum[1] + wsum[2] + wsum[3] + wsum[4] + wsum[5];
        s_scale = 1.0f / fmaxf(sqrtf(tot), EPSN);
    }
    __syncthreads();
    float sc = s_scale;
    ((float4*)dst)[t] = make_float4(v.x * sc, v.y * sc, v.z * sc, v.w * sc);
}

// Fused GEMM + row-max. C-tile 128x128, K-slab 8, 256 threads, 8x8 microtile.
__global__ __launch_bounds__(256) void gemm_max_kernel() {
    __shared__ float As[BK][BM];
    __shared__ float Bs[BK][BN];
    __shared__ float smax[BM][16];

    const int bm = blockIdx.y * BM;
    const int bn = blockIdx.x * BN;
    const int tid = threadIdx.x;
    const int tx = tid & 15;        // 0..15 -> N microtile
    const int ty = tid >> 4;        // 0..15 -> M microtile

    // Global tile loaders: 256 threads fetch 128 rows x 2 float4 (= 128x8 slab).
    const int lrow  = tid >> 1;          // 0..127
    const int lcol4 = (tid & 1) * 4;     // 0 or 4
    const float* __restrict__ Ag = g_exn + (size_t)(bm + lrow) * DIM + lcol4;
    const float* __restrict__ Bg = g_eyn + (size_t)(bn + lrow) * DIM + lcol4;

    float acc[TM][TN];
    #pragma unroll
    for (int i = 0; i < TM; i++)
        #pragma unroll
        for (int j = 0; j < TN; j++) acc[i][j] = 0.0f;

    for (int k0 = 0; k0 < DIM; k0 += BK) {
        float4 a = *(const float4*)(Ag + k0);
        float4 b = *(const float4*)(Bg + k0);
        __syncthreads();                 // previous tile fully consumed
        As[lcol4 + 0][lrow] = a.x;
        As[lcol4 + 1][lrow] = a.y;
        As[lcol4 + 2][lrow] = a.z;
        As[lcol4 + 3][lrow] = a.w;
        Bs[lcol4 + 0][lrow] = b.x;
        Bs[lcol4 + 1][lrow] = b.y;
        Bs[lcol4 + 2][lrow] = b.z;
        Bs[lcol4 + 3][lrow] = b.w;
        __syncthreads();

        #pragma unroll
        for (int kk = 0; kk < BK; kk++) {
            // split 8 = 4 + 4 at stride 64 -> conflict-free LDS.128
            float4 a0 = *(const float4*)&As[kk][ty * 4];
            float4 a1 = *(const float4*)&As[kk][64 + ty * 4];
            float4 b0 = *(const float4*)&Bs[kk][tx * 4];
            float4 b1 = *(const float4*)&Bs[kk][64 + tx * 4];
            float ar[TM] = {a0.x, a0.y, a0.z, a0.w, a1.x, a1.y, a1.z, a1.w};
            float br[TN] = {b0.x, b0.y, b0.z, b0.w, b1.x, b1.y, b1.z, b1.w};
            #pragma unroll
            for (int i = 0; i < TM; i++)
                #pragma unroll
                for (int j = 0; j < TN; j++)
                    acc[i][j] = fmaf(ar[i], br[j], acc[i][j]);
        }
    }

    // Per-thread row max over its 8 columns.
    float rmax[TM];
    #pragma unroll
    for (int i = 0; i < TM; i++) {
        float m = acc[i][0];
        #pragma unroll
        for (int j = 1; j < TN; j++) m = fmaxf(m, acc[i][j]);
        rmax[i] = m;
    }
    __syncthreads();   // done with As/Bs; also ensures smax writes don't race prior loop

    // Microtile rows: ty*4+i (i<4) and 64+ty*4+(i-4).
    #pragma unroll
    for (int i = 0; i < 4; i++) {
        smax[ty * 4 + i][tx]      = rmax[i];
        smax[64 + ty * 4 + i][tx] = rmax[i + 4];
    }
    __syncthreads();

    if (tid < BM) {
        float m = smax[tid][0];
        #pragma unroll
        for (int c = 1; c < 16; c++) m = fmaxf(m, smax[tid][c]);
        atomicMax(&g_keys[bm + tid], fkey(m));
    }
}

__global__ void decode_kernel(float* __restrict__ out) {
    int i = blockIdx.x * blockDim.x + threadIdx.x;
    if (i < NROWS) {
        unsigned int k = g_keys[i];
        unsigned int b = (k & 0x80000000u) ? (k ^ 0x80000000u) : ~k;
        out[i] = __uint_as_float(b);
    }
}

extern "C" void kernel_launch(void* const* d_in, const int* in_sizes, int n_in,
                              void* d_out, int out_size)
{
    const float* ex = (const float*)d_in[0];
    const float* ey = (const float*)d_in[1];
    float* out = (float*)d_out;

    init_keys_kernel<<<(NROWS + 255) / 256, 256>>>();
    normalize_kernel<<<2 * NROWS, 192>>>(ex, ey);
    dim3 grid(NROWS / BN, NROWS / BM);
    gemm_max_kernel<<<grid, 256>>>();
    decode_kernel<<<(NROWS + 255) / 256, 256>>>(out);
}

// round 10
// speedup vs baseline: 4.0535x; 4.0535x over previous
#include <cuda_runtime.h>
#include <stdint.h>

#define NROWS 8192
#define DIM   768
#define EPSN  1e-8f

#define BM 128
#define BN 256
#define BK 32
#define NSLAB (DIM / BK)          // 24

#define A_BYTES (BM * BK * 4)     // 16384
#define B_BYTES (BN * BK * 4)     // 32768
#define STAGE_BYTES (A_BYTES + B_BYTES)   // 49152
#define SMEMSZ (2 * STAGE_BYTES)          // 98304

// ---- device scratch (allocation-free) ----
__device__ __align__(16) float g_xn[(size_t)NROWS * DIM];
__device__ __align__(16) float g_yn[(size_t)NROWS * DIM];
__device__ unsigned int g_keys[NROWS];

__device__ __forceinline__ uint32_t smem_u32(const void* p) {
    uint32_t a;
    asm("{ .reg .u64 t; cvta.to.shared.u64 t, %1; cvt.u32.u64 %0, t; }" : "=r"(a) : "l"(p));
    return a;
}
__device__ __forceinline__ unsigned int fkey(float f) {
    unsigned int b = __float_as_uint(f);
    return (b & 0x80000000u) ? ~b : (b | 0x80000000u);
}
__device__ __forceinline__ uint32_t to_tf32(float x) {
    uint32_t u;
    asm("cvt.rna.tf32.f32 %0, %1;" : "=r"(u) : "f"(x));
    return u;
}
#define CP_ASYNC16(dst, src) \
    asm volatile("cp.async.cg.shared.global [%0], [%1], 16;" :: "r"(dst), "l"(src) : "memory")
#define CP_COMMIT() asm volatile("cp.async.commit_group;" ::: "memory")
#define CP_WAIT0()  asm volatile("cp.async.wait_group 0;" ::: "memory")

#define LDSM4(r0, r1, r2, r3, a) \
    asm volatile("ldmatrix.sync.aligned.m8n8.x4.shared.b16 {%0,%1,%2,%3}, [%4];" \
        : "=r"(r0), "=r"(r1), "=r"(r2), "=r"(r3) : "r"(a))

#define MMA_TF32(c, a0, a1, a2, a3, b0, b1) \
    asm volatile("mma.sync.aligned.m16n8k8.row.col.f32.tf32.tf32.f32 " \
        "{%0,%1,%2,%3}, {%4,%5,%6,%7}, {%8,%9}, {%0,%1,%2,%3};" \
        : "+f"((c)[0]), "+f"((c)[1]), "+f"((c)[2]), "+f"((c)[3]) \
        : "r"(a0), "r"(a1), "r"(a2), "r"(a3), "r"(b0), "r"(b1))

// swizzled byte offset for (row, 16B-chunk) in a [rows][32 f32] tile
__device__ __forceinline__ uint32_t swz(int row, int chunk) {
    return (uint32_t)(row * 128 + ((chunk ^ (row & 7)) << 4));
}

// ---------------------------------------------------------------------------
__global__ void init_keys_kernel() {
    int i = blockIdx.x * blockDim.x + threadIdx.x;
    if (i < NROWS) g_keys[i] = 0u;
}

// Normalize each row (fp32), round to tf32, store fp32-with-zeroed-low-bits.
__global__ __launch_bounds__(192) void normalize_kernel(
    const float* __restrict__ ex, const float* __restrict__ ey)
{
    int row = blockIdx.x;
    bool isx = row < NROWS;
    const float* src = isx ? (ex + (size_t)row * DIM) : (ey + (size_t)(row - NROWS) * DIM);
    float* dst = isx ? (g_xn + (size_t)row * DIM) : (g_yn + (size_t)(row - NROWS) * DIM);

    int t = threadIdx.x;
    float4 v = ((const float4*)src)[t];
    float ss = v.x * v.x + v.y * v.y + v.z * v.z + v.w * v.w;
    #pragma unroll
    for (int o = 16; o > 0; o >>= 1) ss += __shfl_xor_sync(0xffffffffu, ss, o);

    __shared__ float wsum[6];
    __shared__ float s_scale;
    int w = t >> 5, l = t & 31;
    if (l == 0) wsum[w] = ss;
    __syncthreads();
    if (t == 0) {
        float tot = wsum[0] + wsum[1] + wsum[2] + wsum[3] + wsum[4] + wsum[5];
        s_scale = 1.0f / fmaxf(sqrtf(tot), EPSN);
    }
    __syncthreads();
    float sc = s_scale;
    uint4 o;
    o.x = to_tf32(v.x * sc);
    o.y = to_tf32(v.y * sc);
    o.z = to_tf32(v.z * sc);
    o.w = to_tf32(v.w * sc);
    ((uint4*)dst)[t] = o;
}

// Fused tf32 mma.sync GEMM + row-max. CTA 128x256, 8 warps, warp tile 64x64.
__global__ void __launch_bounds__(256, 1) gemm_max_kernel() {
    extern __shared__ char smem[];
    const uint32_t sb = smem_u32(smem);
    const int tid = threadIdx.x;
    const int wid = tid >> 5, lane = tid & 31;
    const int bm = blockIdx.y * BM;
    const int bn = blockIdx.x * BN;
    const int WM = (wid & 1) * 64;   // warp M offset in CTA tile
    const int WN = (wid >> 1) * 64;  // warp N offset

    // ---- load helpers ----
    const int arow = tid >> 3, achk = tid & 7;     // A: 4 iters cover 128x8 chunks
    const float* gA0 = g_xn + (size_t)(bm + arow) * DIM + achk * 4;
    const float* gB0 = g_yn + (size_t)(bn + arow) * DIM + achk * 4;

    float acc[4][8][4];
    #pragma unroll
    for (int i = 0; i < 4; i++)
        #pragma unroll
        for (int j = 0; j < 8; j++)
            #pragma unroll
            for (int c = 0; c < 4; c++) acc[i][j][c] = 0.0f;

    // prologue: load slab 0 into stage 0
    {
        uint32_t abase = sb, bbase = sb + A_BYTES;
        #pragma unroll
        for (int it = 0; it < 4; it++)
            CP_ASYNC16(abase + swz(arow + it * 32, achk), gA0 + (size_t)(it * 32) * DIM);
        #pragma unroll
        for (int it = 0; it < 8; it++)
            CP_ASYNC16(bbase + swz(arow + it * 32, achk), gB0 + (size_t)(it * 32) * DIM);
        CP_COMMIT();
    }

    // per-lane ldmatrix row/chunk decomposition
    const int a_r = lane & 15;              // A frag row within m16
    const int a_cp = lane >> 4;             // A chunk parity (0/1)
    const int b_r = ((lane >> 4) << 3) + (lane & 7);   // B row within n16
    const int b_cp = (lane >> 3) & 1;       // B chunk parity

    for (int s = 0; s < NSLAB; s++) {
        CP_WAIT0();
        __syncthreads();

        if (s + 1 < NSLAB) {
            const size_t kof = (size_t)(s + 1) * BK;
            uint32_t st = sb + ((s + 1) & 1) * STAGE_BYTES;
            uint32_t abase = st, bbase = st + A_BYTES;
            #pragma unroll
            for (int it = 0; it < 4; it++)
                CP_ASYNC16(abase + swz(arow + it * 32, achk), gA0 + (size_t)(it * 32) * DIM + kof);
            #pragma unroll
            for (int it = 0; it < 8; it++)
                CP_ASYNC16(bbase + swz(arow + it * 32, achk), gB0 + (size_t)(it * 32) * DIM + kof);
            CP_COMMIT();
        }

        const uint32_t st = sb + (s & 1) * STAGE_BYTES;
        const uint32_t abase = st, bbase = st + A_BYTES;

        #pragma unroll
        for (int ks = 0; ks < 4; ks++) {
            uint32_t afr[4][4], bfr[4][4];
            #pragma unroll
            for (int mi = 0; mi < 4; mi++) {
                int r = WM + mi * 16 + a_r;
                LDSM4(afr[mi][0], afr[mi][1], afr[mi][2], afr[mi][3],
                      abase + swz(r, ks * 2 + a_cp));
            }
            #pragma unroll
            for (int nj = 0; nj < 4; nj++) {
                int r = WN + nj * 16 + b_r;
                LDSM4(bfr[nj][0], bfr[nj][1], bfr[nj][2], bfr[nj][3],
                      bbase + swz(r, ks * 2 + b_cp));
            }
            #pragma unroll
            for (int mi = 0; mi < 4; mi++)
                #pragma unroll
                for (int nj = 0; nj < 4; nj++) {
                    MMA_TF32(acc[mi][nj * 2],
                             afr[mi][0], afr[mi][1], afr[mi][2], afr[mi][3],
                             bfr[nj][0], bfr[nj][1]);
                    MMA_TF32(acc[mi][nj * 2 + 1],
                             afr[mi][0], afr[mi][1], afr[mi][2], afr[mi][3],
                             bfr[nj][2], bfr[nj][3]);
                }
        }
        __syncthreads();
    }

    // ---- epilogue: row max + atomicMax on order-preserving keys ----
    #pragma unroll
    for (int mi = 0; mi < 4; mi++) {
        float m0 = -2.0f, m1 = -2.0f;
        #pragma unroll
        for (int nb = 0; nb < 8; nb++) {
            m0 = fmaxf(m0, fmaxf(acc[mi][nb][0], acc[mi][nb][1]));
            m1 = fmaxf(m1, fmaxf(acc[mi][nb][2], acc[mi][nb][3]));
        }
        // reduce across the 4 lanes of a row-quad (they cover different cols)
        #pragma unroll
        for (int o = 1; o < 4; o <<= 1) {
            m0 = fmaxf(m0, __shfl_xor_sync(0xffffffffu, m0, o));
            m1 = fmaxf(m1, __shfl_xor_sync(0xffffffffu, m1, o));
        }
        if ((lane & 3) == 0) {
            int row0 = bm + WM + mi * 16 + (lane >> 2);
            atomicMax(&g_keys[row0],     fkey(m0));
            atomicMax(&g_keys[row0 + 8], fkey(m1));
        }
    }
}

__global__ void decode_kernel(float* __restrict__ out) {
    int i = blockIdx.x * blockDim.x + threadIdx.x;
    if (i < NROWS) {
        unsigned int k = g_keys[i];
        unsigned int b = (k & 0x80000000u) ? (k ^ 0x80000000u) : ~k;
        out[i] = __uint_as_float(b);
    }
}

extern "C" void kernel_launch(void* const* d_in, const int* in_sizes, int n_in,
                              void* d_out, int out_size)
{
    const float* ex = (const float*)d_in[0];
    const float* ey = (const float*)d_in[1];
    float* out = (float*)d_out;

    // Unconditional (no static guards — harness forbids call-count behavior).
    cudaFuncSetAttribute(gemm_max_kernel,
                         cudaFuncAttributeMaxDynamicSharedMemorySize, SMEMSZ);

    init_keys_kernel<<<(NROWS + 255) / 256, 256>>>();
    normalize_kernel<<<2 * NROWS, 192>>>(ex, ey);
    dim3 grid(NROWS / BN, NROWS / BM);   // 32 x 64
    gemm_max_kernel<<<grid, 256, SMEMSZ>>>();
    decode_kernel<<<(NROWS + 255) / 256, 256>>>(out);
}